// round 6
// baseline (speedup 1.0000x reference)
#include <cuda_runtime.h>

#define W_IMG  1248
#define NROWS  768
#define SEG    320            // outputs per warp-segment (4 segs/row)
#define HALO   192
#define NT     128            // 4 warps = 4 segments = 1 row per CTA
#define C      16             // elements per thread; 192 = 12*16 exactly

__global__ __launch_bounds__(NT, 8) void stereo_warp6_kernel(
    const float* __restrict__ L,
    const float* __restrict__ R,
    float* __restrict__ out)
{
    const int row  = blockIdx.x;
    const int tid  = threadIdx.x;
    const int lane = tid & 31;
    const int seg  = tid >> 5;                 // 0..3

    const float* __restrict__ r = R + (size_t)row * W_IMG;
    const float* __restrict__ l = L + (size_t)row * W_IMG;
    float* __restrict__ o = out + (size_t)row * W_IMG;

    const int u0 = lane * C;                   // local coord base (0..496)
    const int j0 = seg * SEG - HALO + u0;      // global column of this chunk
    // whole-chunk predicates (all boundaries multiples of 16)
    const bool inr  = (j0 >= 0) && (j0 + C <= W_IMG);        // r-load validity
    const bool outv = (u0 >= HALO) && (j0 + C <= W_IMG);     // output validity

    // ---- r loads (4 x LDG.128) ----
    float rv[C];
    if (inr) {
        #pragma unroll
        for (int v = 0; v < 4; v++)
            *(float4*)(rv + 4 * v) = *(const float4*)(r + j0 + 4 * v);
    } else {
        #pragma unroll
        for (int s = 0; s < C; s++) rv[s] = 0.f;
    }

    // ---- serial scan of 16-chunk in local coords (rv consumed -> lp/lq) ----
    float lp[C], lq[C];
    float p = 0.f, q = 0.f;
    #pragma unroll
    for (int s = 0; s < C; s++) {
        p += rv[s];
        q = fmaf((float)(u0 + s), rv[s], q);
        lp[s] = p;
        lq[s] = q;
    }

    // ---- l loads issued now: latency overlaps the shuffle-scan chain ----
    float lv[C];
    if (outv) {
        #pragma unroll
        for (int v = 0; v < 4; v++)
            *(float4*)(lv + 4 * v) = *(const float4*)(l + j0 + 4 * v);
    }

    // ---- inclusive warp scan of (p, q) thread totals ----
    float vp = p, vq = q;
    #pragma unroll
    for (int off = 1; off < 32; off <<= 1) {
        float ap = __shfl_up_sync(0xffffffffu, vp, off);
        float aq = __shfl_up_sync(0xffffffffu, vq, off);
        if (lane >= off) { vp += ap; vq += aq; }
    }
    const float offp = vp - p;
    const float offq = vq - q;
    #pragma unroll
    for (int s = 0; s < C; s++) { lp[s] += offp; lq[s] += offq; }

    // ---- outputs: prefix at u-192 = same position s, lane-12 ----
    #pragma unroll
    for (int s = 0; s < C; s++) {
        float bp = __shfl_up_sync(0xffffffffu, lp[s], 12);
        float bq = __shfl_up_sync(0xffffffffu, lq[s], 12);
        float S  = (float)(u0 + s) * (lp[s] - bp) - (lq[s] - bq);
        lv[s] = lv[s] * S;                     // result in place of lv
    }

    if (outv) {
        #pragma unroll
        for (int v = 0; v < 4; v++)
            *(float4*)(o + j0 + 4 * v) = *(const float4*)(lv + 4 * v);
    }
}

extern "C" void kernel_launch(void* const* d_in, const int* in_sizes, int n_in,
                              void* d_out, int out_size)
{
    const float* left  = (const float*)d_in[0];
    const float* right = (const float*)d_in[1];
    float* out = (float*)d_out;
    stereo_warp6_kernel<<<NROWS, NT>>>(left, right, out);
}

// round 7
// speedup vs baseline: 1.3755x; 1.3755x over previous
#include <cuda_runtime.h>

#define W_IMG  1248
#define NROWS  768
#define SEGW   192            // outputs per warp-segment
#define NSEG   7              // ceil(1248 / 192) -> covers 1344, tail masked
#define HALO   192
#define NT     128            // 4 warps = 4 rows per CTA (same segment)
#define C      12             // elements per thread; 192 = 16*12 exactly

__global__ __launch_bounds__(NT) void stereo_c12_kernel(
    const float* __restrict__ L,
    const float* __restrict__ R,
    float* __restrict__ out)
{
    const int tid  = threadIdx.x;
    const int lane = tid & 31;
    const int warp = tid >> 5;
    const int row  = blockIdx.x * 4 + warp;   // 192*4 = 768 rows
    const int seg  = blockIdx.y;              // 0..6

    const float* __restrict__ r = R + (size_t)row * W_IMG;
    const float* __restrict__ l = L + (size_t)row * W_IMG;
    float* __restrict__ o = out + (size_t)row * W_IMG;

    const int u0 = lane * C;                  // local coord base (0..372)
    const int j0 = seg * SEGW - HALO + u0;    // global column of this chunk
    // whole-chunk predicates: j0 is a multiple of 12 and 1248 = 104*12
    const bool inr  = (j0 >= 0) && (j0 + C <= W_IMG);     // r-load validity
    const bool outv = (u0 >= HALO) && (j0 + C <= W_IMG);  // output validity

    // ---- r loads (3 x LDG.128) ----
    float rv[C];
    if (inr) {
        #pragma unroll
        for (int v = 0; v < 3; v++)
            *(float4*)(rv + 4 * v) = *(const float4*)(r + j0 + 4 * v);
    } else {
        #pragma unroll
        for (int s = 0; s < C; s++) rv[s] = 0.f;
    }
    // ---- l loads issued immediately too (latency overlaps scan) ----
    float lv[C];
    if (outv) {
        #pragma unroll
        for (int v = 0; v < 3; v++)
            *(float4*)(lv + 4 * v) = *(const float4*)(l + j0 + 4 * v);
    }

    // ---- serial scan of 12-chunk in local coords ----
    float lp[C], lq[C];
    float p = 0.f, q = 0.f;
    #pragma unroll
    for (int s = 0; s < C; s++) {
        p += rv[s];
        q = fmaf((float)(u0 + s), rv[s], q);
        lp[s] = p;
        lq[s] = q;
    }

    // ---- inclusive warp scan of (p, q) thread totals ----
    float vp = p, vq = q;
    #pragma unroll
    for (int off = 1; off < 32; off <<= 1) {
        float ap = __shfl_up_sync(0xffffffffu, vp, off);
        float aq = __shfl_up_sync(0xffffffffu, vq, off);
        if (lane >= off) { vp += ap; vq += aq; }
    }
    const float offp = vp - p;
    const float offq = vq - q;
    #pragma unroll
    for (int s = 0; s < C; s++) { lp[s] += offp; lq[s] += offq; }

    // ---- outputs: prefix at u-192 = same position s, lane-16 ----
    #pragma unroll
    for (int s = 0; s < C; s++) {
        float bp = __shfl_up_sync(0xffffffffu, lp[s], 16);
        float bq = __shfl_up_sync(0xffffffffu, lq[s], 16);
        float S  = (float)(u0 + s) * (lp[s] - bp) - (lq[s] - bq);
        lv[s] = lv[s] * S;                    // result in place of lv
    }

    if (outv) {
        #pragma unroll
        for (int v = 0; v < 3; v++)
            *(float4*)(o + j0 + 4 * v) = *(const float4*)(lv + 4 * v);
    }
}

extern "C" void kernel_launch(void* const* d_in, const int* in_sizes, int n_in,
                              void* d_out, int out_size)
{
    const float* left  = (const float*)d_in[0];
    const float* right = (const float*)d_in[1];
    float* out = (float*)d_out;
    dim3 grid(NROWS / 4, NSEG);
    stereo_c12_kernel<<<grid, NT>>>(left, right, out);
}

// round 8
// speedup vs baseline: 1.4160x; 1.0294x over previous
#include <cuda_runtime.h>

#define W_IMG  1248
#define NROWS  768
#define SEGW   192            // outputs per warp-segment
#define NSEG   7              // 7*192 = 1344 >= 1248, tail masked
#define HALO   192
#define NT     128            // 4 warps = 4 rows per CTA (same segment)
#define C      12             // elements per thread; 192 = 16*12 exactly

__global__ __launch_bounds__(NT) void stereo_c12b_kernel(
    const float* __restrict__ L,
    const float* __restrict__ R,
    float* __restrict__ out)
{
    const int tid  = threadIdx.x;
    const int lane = tid & 31;
    const int warp = tid >> 5;
    const int row  = blockIdx.x * 4 + warp;   // 192*4 = 768 rows
    const int seg  = blockIdx.y;              // 0..6

    const float* __restrict__ r = R + (size_t)row * W_IMG;
    const float* __restrict__ l = L + (size_t)row * W_IMG;
    float* __restrict__ o = out + (size_t)row * W_IMG;

    const int u0 = lane * C;                  // local coord base (0..372)
    const int j0 = seg * SEGW - HALO + u0;    // global column of this chunk
    // whole-chunk predicates: j0 is a multiple of 12 and 1248 = 104*12
    const bool inr  = (j0 >= 0) && (j0 + C <= W_IMG);     // r-load validity
    const bool outv = (u0 >= HALO) && (j0 + C <= W_IMG);  // output validity

    // ---- r loads (3 x LDG.128) ----
    float rv[C];
    if (inr) {
        #pragma unroll
        for (int v = 0; v < 3; v++)
            *(float4*)(rv + 4 * v) = *(const float4*)(r + j0 + 4 * v);
    } else {
        #pragma unroll
        for (int s = 0; s < C; s++) rv[s] = 0.f;
    }
    // ---- l loads issued immediately (latency overlaps scan) ----
    float lv[C];
    if (outv) {
        #pragma unroll
        for (int v = 0; v < 3; v++)
            *(float4*)(lv + 4 * v) = *(const float4*)(l + j0 + 4 * v);
    }

    // ---- serial scan of 12-chunk in local coords ----
    float lp[C], lq[C];
    {
        float p = 0.f, q = 0.f;
        const float u0f = (float)u0;
        #pragma unroll
        for (int s = 0; s < C; s++) {
            p += rv[s];
            q = fmaf(u0f + (float)s, rv[s], q);
            lp[s] = p;
            lq[s] = q;
        }

        // ---- inclusive warp scan of (p, q) thread totals ----
        float vp = p, vq = q;
        #pragma unroll
        for (int off = 1; off < 32; off <<= 1) {
            float ap = __shfl_up_sync(0xffffffffu, vp, off);
            float aq = __shfl_up_sync(0xffffffffu, vq, off);
            if (lane >= off) { vp += ap; vq += aq; }
        }
        const float offp = vp - p;
        const float offq = vq - q;
        #pragma unroll
        for (int s = 0; s < C; s++) { lp[s] += offp; lq[s] += offq; }
    }

    // ---- outputs with producer-side combine: one shuffle per s ----
    // Producer lane (lane-16) computes T = (u_prod + 192)*lp - lq, which IS
    // the consumer's  u*bp - bq  term. Consumer: S = (u*lp - lq) - T_recv.
    {
        const float cA = (float)(u0 + HALO);   // producer-side coefficient base
        const float cB = (float)u0;            // consumer-side coefficient base
        #pragma unroll
        for (int s = 0; s < C; s++) {
            float T  = fmaf(cA + (float)s, lp[s], -lq[s]);   // every lane produces
            float bT = __shfl_up_sync(0xffffffffu, T, 16);
            float S  = fmaf(cB + (float)s, lp[s], -lq[s]) - bT;
            lv[s] = lv[s] * S;
        }
    }

    if (outv) {
        #pragma unroll
        for (int v = 0; v < 3; v++)
            *(float4*)(o + j0 + 4 * v) = *(const float4*)(lv + 4 * v);
    }
}

extern "C" void kernel_launch(void* const* d_in, const int* in_sizes, int n_in,
                              void* d_out, int out_size)
{
    const float* left  = (const float*)d_in[0];
    const float* right = (const float*)d_in[1];
    float* out = (float*)d_out;
    dim3 grid(NROWS / 4, NSEG);
    stereo_c12b_kernel<<<grid, NT>>>(left, right, out);
}